// round 7
// baseline (speedup 1.0000x reference)
#include <cuda_runtime.h>
#include <math.h>

#define HIDDEN 2048
#define NUM_HEADS 16
#define HEAD_DIM 128
#define BLOCK_SIZE 64
#define NUM_SEQS 64
#define MAX_SEQ_LEN 2048
#define MAX_BLOCKS 32
#define NUM_BLOCKS_KV 2048
#define SCALE 0.08838834764831843f   // 1/sqrt(128)

#define KSPLIT 16
#define PART 32            // one KV page (64 tokens) per partition

// Scratch (device globals; no allocation allowed)
__device__ float g_q[NUM_SEQS * HIDDEN];                   // Q projection result
__device__ float g_attn[NUM_SEQS * HIDDEN];                // attention output
__device__ float g_part[KSPLIT * NUM_SEQS * HIDDEN];       // split-K partials
__device__ float g_pacc[NUM_SEQS * NUM_HEADS * PART * HEAD_DIM]; // attn partial accum (16MB)
__device__ float2 g_pml[NUM_SEQS * NUM_HEADS * PART];      // attn partial (m, l)

__device__ __forceinline__ float4 ldcs4(const float* p) {
    return __ldcs((const float4*)p);
}

// ---------------------------------------------------------------------------
// Split-K GEMM: tile 64M x 128N, BK=16, 256 threads, thread tile 8M x 4N
// ---------------------------------------------------------------------------
__global__ __launch_bounds__(256) void gemm_splitk(
    const float* __restrict__ A, const float* __restrict__ B,
    float* __restrict__ P, int K, int ldb, int N)
{
    const int KS = K / KSPLIT;              // 128
    const int k_base = blockIdx.y * KS;
    const int n0 = blockIdx.x * 128;

    __shared__ float As[64][17];
    __shared__ float Bs[16][128];

    const int tid = threadIdx.x;
    const int tx = tid & 31;   // N dir (x4)  -> 128 N
    const int ty = tid >> 5;   // M dir (x8)  -> 64 M

    const int a_row = tid >> 2;          // 0..63
    const int a_c4  = (tid & 3) * 4;     // 0,4,8,12
    const int b_row0 = tid >> 5;         // 0..7 (first half), +8 second
    const int b_c4   = (tid & 31) * 4;   // 0..124

    float acc[8][4];
#pragma unroll
    for (int i = 0; i < 8; i++)
#pragma unroll
        for (int j = 0; j < 4; j++) acc[i][j] = 0.f;

    float4 ra  = *(const float4*)&A[a_row * K + k_base + a_c4];
    float4 rb0 = *(const float4*)&B[(size_t)(k_base + b_row0) * ldb + n0 + b_c4];
    float4 rb1 = *(const float4*)&B[(size_t)(k_base + b_row0 + 8) * ldb + n0 + b_c4];

    for (int k0 = k_base; k0 < k_base + KS; k0 += 16) {
        As[a_row][a_c4 + 0] = ra.x;
        As[a_row][a_c4 + 1] = ra.y;
        As[a_row][a_c4 + 2] = ra.z;
        As[a_row][a_c4 + 3] = ra.w;
        *(float4*)&Bs[b_row0][b_c4]     = rb0;
        *(float4*)&Bs[b_row0 + 8][b_c4] = rb1;
        __syncthreads();

        if (k0 + 16 < k_base + KS) {
            int kn = k0 + 16;
            ra  = *(const float4*)&A[a_row * K + kn + a_c4];
            rb0 = *(const float4*)&B[(size_t)(kn + b_row0) * ldb + n0 + b_c4];
            rb1 = *(const float4*)&B[(size_t)(kn + b_row0 + 8) * ldb + n0 + b_c4];
        }

#pragma unroll
        for (int kk = 0; kk < 16; kk++) {
            float4 b4 = *(const float4*)&Bs[kk][tx * 4];
            float a[8];
#pragma unroll
            for (int i = 0; i < 8; i++) a[i] = As[ty * 8 + i][kk];
#pragma unroll
            for (int i = 0; i < 8; i++) {
                acc[i][0] += a[i] * b4.x;
                acc[i][1] += a[i] * b4.y;
                acc[i][2] += a[i] * b4.z;
                acc[i][3] += a[i] * b4.w;
            }
        }
        __syncthreads();
    }

    float* Pp = P + (size_t)blockIdx.y * 64 * N;
#pragma unroll
    for (int i = 0; i < 8; i++) {
        float4 v = make_float4(acc[i][0], acc[i][1], acc[i][2], acc[i][3]);
        *(float4*)&Pp[(ty * 8 + i) * N + n0 + tx * 4] = v;
    }
}

// reduce KSPLIT partials + bias (float4 vectorized; MLP=16)
__global__ __launch_bounds__(256) void reduceK(
    const float4* __restrict__ P, const float4* __restrict__ bias,
    float4* __restrict__ C, int N4, int total4)
{
    int i = blockIdx.x * blockDim.x + threadIdx.x;
    if (i < total4) {
        float4 v = bias[i & (N4 - 1)];
        float4 t[KSPLIT];
#pragma unroll
        for (int p = 0; p < KSPLIT; p++) t[p] = P[(size_t)p * total4 + i];
#pragma unroll
        for (int p = 0; p < KSPLIT; p++) {
            v.x += t[p].x; v.y += t[p].y; v.z += t[p].z; v.w += t[p].w;
        }
        C[i] = v;
    }
}

// ---------------------------------------------------------------------------
// Page-streaming attention: block = (seq, page). All 16 heads per block.
// Pass 1 uses a multi-value butterfly reduce: 16 SHFLs/token instead of 80.
// ---------------------------------------------------------------------------
__global__ __launch_bounds__(256) void attn_part_kernel(
    const float* __restrict__ kv_cache,      // [2, NB, bs, h, d]
    const int* __restrict__ block_tables,    // [S, MAX_BLOCKS]
    const int* __restrict__ seq_lens,        // [S]
    const float* __restrict__ qbuf)          // [S, HIDDEN]
{
    const int s = blockIdx.x;
    const int p = blockIdx.y;
    const int tid = threadIdx.x;
    const int warp = tid >> 5;
    const int lane = tid & 31;

    const int L  = seq_lens[s];
    const int Lp = min(L - p * BLOCK_SIZE, BLOCK_SIZE);
    if (Lp <= 0) return;                     // combine never reads empty pages

    const int blk = __ldg(&block_tables[s * MAX_BLOCKS + p]);

    __shared__ float q[NUM_HEADS * HEAD_DIM];        // 8KB
    __shared__ float scores[NUM_HEADS * BLOCK_SIZE]; // 4KB  [h][t]
    __shared__ float red[8][NUM_HEADS];
    __shared__ float gmaxs[NUM_HEADS];
    __shared__ float lsums[NUM_HEADS];
    __shared__ float accbuf[8][8 * HEAD_DIM];        // 32KB

    // load q for all heads (2048 floats = 512 float4)
    ((float4*)q)[tid]       = ((const float4*)(qbuf + s * HIDDEN))[tid];
    ((float4*)q)[tid + 256] = ((const float4*)(qbuf + s * HIDDEN))[tid + 256];
    __syncthreads();

    const float* kpage = kv_cache + (size_t)blk * BLOCK_SIZE * HIDDEN;
    const float* vpage = kpage + (size_t)NUM_BLOCKS_KV * BLOCK_SIZE * HIDDEN;

    // ---- Pass 1: scores for all heads; warp = token (stride 8) ----
    // After the butterfly, lane pair (2h, 2h+1) holds head h's score.
    const int myh  = (lane >> 1) & 15;      // head owned by this lane
    const int b4 = lane & 16, b3 = lane & 8, b2 = lane & 4, b1 = lane & 2;
    float mymax = -INFINITY;

    for (int t = warp; t < Lp; t += 8) {
        const float* row = kpage + (size_t)t * HIDDEN + lane * 4;
        float pp[NUM_HEADS];
#pragma unroll
        for (int h = 0; h < NUM_HEADS; h++) {
            float4 k4 = ldcs4(row + h * HEAD_DIM);
            float4 qh = *(const float4*)&q[h * HEAD_DIM + lane * 4];
            pp[h] = qh.x * k4.x + qh.y * k4.y + qh.z * k4.z + qh.w * k4.w;
        }
        // butterfly multi-reduce: 16 values -> 1 per lane, 16 SHFLs
        float s8[8];
#pragma unroll
        for (int i = 0; i < 8; i++) {
            float keep = b4 ? pp[i + 8] : pp[i];
            float send = b4 ? pp[i]     : pp[i + 8];
            s8[i] = keep + __shfl_xor_sync(0xffffffffu, send, 16);
        }
        float s4[4];
#pragma unroll
        for (int i = 0; i < 4; i++) {
            float keep = b3 ? s8[i + 4] : s8[i];
            float send = b3 ? s8[i]     : s8[i + 4];
            s4[i] = keep + __shfl_xor_sync(0xffffffffu, send, 8);
        }
        float s2[2];
#pragma unroll
        for (int i = 0; i < 2; i++) {
            float keep = b2 ? s4[i + 2] : s4[i];
            float send = b2 ? s4[i]     : s4[i + 2];
            s2[i] = keep + __shfl_xor_sync(0xffffffffu, send, 4);
        }
        float s1;
        {
            float keep = b1 ? s2[1] : s2[0];
            float send = b1 ? s2[0] : s2[1];
            s1 = keep + __shfl_xor_sync(0xffffffffu, send, 2);
        }
        float sc = (s1 + __shfl_xor_sync(0xffffffffu, s1, 1)) * SCALE;

        if (!(lane & 1)) scores[myh * BLOCK_SIZE + t] = sc;
        mymax = fmaxf(mymax, sc);
    }
    if (!(lane & 1)) red[warp][myh] = mymax;
    __syncthreads();

    if (tid < NUM_HEADS) {
        float m = red[0][tid];
#pragma unroll
        for (int w = 1; w < 8; w++) m = fmaxf(m, red[w][tid]);
        gmaxs[tid] = m;
    }
    __syncthreads();

    // ---- exp + per-head sums: thread tid -> head tid>>4, 4 tokens ----
    {
        int h = tid >> 4, ii = tid & 15;
        float gm = gmaxs[h];
        float part = 0.f;
#pragma unroll
        for (int j = 0; j < 4; j++) {
            int t = ii * 4 + j;
            if (t < Lp) {
                float e = __expf(scores[h * BLOCK_SIZE + t] - gm);
                scores[h * BLOCK_SIZE + t] = e;
                part += e;
            }
        }
#pragma unroll
        for (int o = 8; o; o >>= 1) part += __shfl_xor_sync(0xffffffffu, part, o);
        if (ii == 0) lsums[h] = part;
    }
    __syncthreads();

    // ---- Pass 2: V accumulate; warp-pair = token, 8 heads per warp ----
    {
        const int g = warp & 1;          // head group (0: h0-7, 1: h8-15)
        float4 acc[8];
#pragma unroll
        for (int i = 0; i < 8; i++) acc[i] = make_float4(0.f, 0.f, 0.f, 0.f);

        for (int t = (warp >> 1); t < Lp; t += 4) {
            const float* row = vpage + (size_t)t * HIDDEN + g * (8 * HEAD_DIM) + lane * 4;
#pragma unroll
            for (int i = 0; i < 8; i++) {
                float w = scores[(g * 8 + i) * BLOCK_SIZE + t];
                float4 v4 = ldcs4(row + i * HEAD_DIM);
                acc[i].x += w * v4.x;
                acc[i].y += w * v4.y;
                acc[i].z += w * v4.z;
                acc[i].w += w * v4.w;
            }
        }
#pragma unroll
        for (int i = 0; i < 8; i++)
            *(float4*)&accbuf[warp][i * HEAD_DIM + lane * 4] = acc[i];
    }
    __syncthreads();

    // ---- final reduce (4 warp-partials per head) + write partials ----
#pragma unroll
    for (int e = 0; e < 8; e++) {
        int idx = tid + e * 256;          // 0..2047 = head*128 + dim
        int h = idx >> 7, d = idx & 127;
        int gg = h >> 3, i = h & 7;
        float sum = accbuf[gg][i * HEAD_DIM + d] + accbuf[gg + 2][i * HEAD_DIM + d]
                  + accbuf[gg + 4][i * HEAD_DIM + d] + accbuf[gg + 6][i * HEAD_DIM + d];
        g_pacc[((size_t)(s * NUM_HEADS + h) * PART + p) * HEAD_DIM + d] = sum;
    }
    if (tid < NUM_HEADS)
        g_pml[(s * NUM_HEADS + tid) * PART + p] = make_float2(gmaxs[tid], lsums[tid]);
}

// ---------------------------------------------------------------------------
// Combine: block = (seq, head), 256 threads. 8 warps each online-merge pages
// p = warp, warp+8, ... (<=4 serial steps), then 128-thread smem merge of 8.
// ---------------------------------------------------------------------------
__global__ __launch_bounds__(256) void attn_combine_kernel(
    const int* __restrict__ seq_lens, float* __restrict__ out)
{
    const int s = blockIdx.x;
    const int h = blockIdx.y;
    const int warp = threadIdx.x >> 5;
    const int lane = threadIdx.x & 31;
    const int base = (s * NUM_HEADS + h) * PART;
    const int nv = min((__ldg(&seq_lens[s]) + BLOCK_SIZE - 1) >> 6, PART);

    __shared__ float m8[8], l8[8];
    __shared__ float obuf[8][HEAD_DIM];

    float m = -INFINITY, l = 0.f;
    float4 o = make_float4(0.f, 0.f, 0.f, 0.f);
    for (int p = warp; p < nv; p += 8) {
        float2 ml = g_pml[base + p];
        float4 pa = *(const float4*)&g_pacc[(size_t)(base + p) * HEAD_DIM + lane * 4];
        if (ml.x > m) {
            float r = __expf(m - ml.x);
            l *= r; o.x *= r; o.y *= r; o.z *= r; o.w *= r;
            m = ml.x;
        }
        float sc = __expf(ml.x - m);
        l += ml.y * sc;
        o.x += pa.x * sc; o.y += pa.y * sc; o.z += pa.z * sc; o.w += pa.w * sc;
    }
    *(float4*)&obuf[warp][lane * 4] = o;
    if (lane == 0) { m8[warp] = m; l8[warp] = l; }
    __syncthreads();

    if (threadIdx.x < HEAD_DIM) {
        int d = threadIdx.x;
        float M = m8[0];
#pragma unroll
        for (int w = 1; w < 8; w++) M = fmaxf(M, m8[w]);
        float L = 0.f, O = 0.f;
#pragma unroll
        for (int w = 0; w < 8; w++) {
            float sc = (m8[w] == -INFINITY) ? 0.f : __expf(m8[w] - M);
            L += l8[w] * sc;
            O += obuf[w][d] * sc;
        }
        out[s * HIDDEN + h * HEAD_DIM + d] = O / L;
    }
}

// ---------------------------------------------------------------------------
extern "C" void kernel_launch(void* const* d_in, const int* in_sizes, int n_in,
                              void* d_out, int out_size)
{
    const float* hidden  = (const float*)d_in[0];
    const float* kvcache = (const float*)d_in[1];
    const float* W_attn  = (const float*)d_in[2];
    const float* b_attn  = (const float*)d_in[3];
    const float* W_proj  = (const float*)d_in[4];
    const float* b_proj  = (const float*)d_in[5];
    const int*   btab    = (const int*)d_in[6];
    const int*   slens   = (const int*)d_in[7];
    float* out = (float*)d_out;

    float *gq, *gattn, *gpart;
    cudaGetSymbolAddress((void**)&gq, g_q);
    cudaGetSymbolAddress((void**)&gattn, g_attn);
    cudaGetSymbolAddress((void**)&gpart, g_part);

    const int total4 = NUM_SEQS * HIDDEN / 4;  // 32768
    const int N4 = HIDDEN / 4;                 // 512

    // 1) Q projection only (first HIDDEN columns of W_attn), split-K=16
    gemm_splitk<<<dim3(HIDDEN / 128, KSPLIT), 256>>>(hidden, W_attn, gpart, HIDDEN, 3 * HIDDEN, HIDDEN);
    reduceK<<<(total4 + 255) / 256, 256>>>((const float4*)gpart, (const float4*)b_attn,
                                           (float4*)gq, N4, total4);

    // 2) paged attention: page-streaming split + combine
    attn_part_kernel<<<dim3(NUM_SEQS, PART), 256>>>(kvcache, btab, slens, gq);
    attn_combine_kernel<<<dim3(NUM_SEQS, NUM_HEADS), 256>>>(slens, gattn);

    // 3) output projection, split-K=16
    gemm_splitk<<<dim3(HIDDEN / 128, KSPLIT), 256>>>(gattn, W_proj, gpart, HIDDEN, HIDDEN, HIDDEN);
    reduceK<<<(total4 + 255) / 256, 256>>>((const float4*)gpart, (const float4*)b_proj,
                                           (float4*)out, N4, total4);
}

// round 8
// speedup vs baseline: 1.1618x; 1.1618x over previous
#include <cuda_runtime.h>
#include <math.h>

#define HIDDEN 2048
#define NUM_HEADS 16
#define HEAD_DIM 128
#define BLOCK_SIZE 64
#define NUM_SEQS 64
#define MAX_SEQ_LEN 2048
#define MAX_BLOCKS 32
#define NUM_BLOCKS_KV 2048
#define SCALE 0.08838834764831843f   // 1/sqrt(128)

#define KSPLIT 8
#define PART 32            // one KV page (64 tokens) per partition

// Scratch (device globals; no allocation allowed)
__device__ float g_q[NUM_SEQS * HIDDEN];                   // Q projection result
__device__ float g_attn[NUM_SEQS * HIDDEN];                // attention output
__device__ float g_part[KSPLIT * NUM_SEQS * HIDDEN];       // split-K partials
__device__ float g_pacc[NUM_SEQS * NUM_HEADS * PART * HEAD_DIM]; // attn partial accum (16MB)
__device__ float2 g_pml[NUM_SEQS * NUM_HEADS * PART];      // attn partial (m, l)

__device__ __forceinline__ float4 ldcs4(const float* p) {
    return __ldcs((const float4*)p);
}

// ---------------------------------------------------------------------------
// Split-K GEMM: tile 64x64, BK=16, 256 threads, thread tile 4x4, split-K=8
// ---------------------------------------------------------------------------
__global__ __launch_bounds__(256) void gemm_splitk(
    const float* __restrict__ A, const float* __restrict__ B,
    float* __restrict__ P, int K, int ldb, int N)
{
    const int KS = K / KSPLIT;              // 256
    const int k_base = blockIdx.y * KS;
    const int n0 = blockIdx.x * 64;

    __shared__ float As[64][17];
    __shared__ float Bs[16][64];

    const int tid = threadIdx.x;
    const int tx = tid & 15;
    const int ty = tid >> 4;

    const int a_row = tid >> 2;
    const int a_c4  = (tid & 3) * 4;
    const int b_row = tid >> 4;
    const int b_c4  = (tid & 15) * 4;

    float acc[4][4];
#pragma unroll
    for (int i = 0; i < 4; i++)
#pragma unroll
        for (int j = 0; j < 4; j++) acc[i][j] = 0.f;

    float4 ra = *(const float4*)&A[a_row * K + k_base + a_c4];
    float4 rb = *(const float4*)&B[(size_t)(k_base + b_row) * ldb + n0 + b_c4];

    for (int k0 = k_base; k0 < k_base + KS; k0 += 16) {
        As[a_row][a_c4 + 0] = ra.x;
        As[a_row][a_c4 + 1] = ra.y;
        As[a_row][a_c4 + 2] = ra.z;
        As[a_row][a_c4 + 3] = ra.w;
        *(float4*)&Bs[b_row][b_c4] = rb;
        __syncthreads();

        if (k0 + 16 < k_base + KS) {
            int kn = k0 + 16;
            ra = *(const float4*)&A[a_row * K + kn + a_c4];
            rb = *(const float4*)&B[(size_t)(kn + b_row) * ldb + n0 + b_c4];
        }

#pragma unroll
        for (int kk = 0; kk < 16; kk++) {
            float4 b4 = *(const float4*)&Bs[kk][tx * 4];
            float a[4];
#pragma unroll
            for (int i = 0; i < 4; i++) a[i] = As[ty * 4 + i][kk];
#pragma unroll
            for (int i = 0; i < 4; i++) {
                acc[i][0] += a[i] * b4.x;
                acc[i][1] += a[i] * b4.y;
                acc[i][2] += a[i] * b4.z;
                acc[i][3] += a[i] * b4.w;
            }
        }
        __syncthreads();
    }

    float* Pp = P + (size_t)blockIdx.y * 64 * N;
#pragma unroll
    for (int i = 0; i < 4; i++) {
        float4 v = make_float4(acc[i][0], acc[i][1], acc[i][2], acc[i][3]);
        *(float4*)&Pp[(ty * 4 + i) * N + n0 + tx * 4] = v;
    }
}

// reduce KSPLIT partials + bias (float4 vectorized; MLP=8)
__global__ __launch_bounds__(256) void reduceK(
    const float4* __restrict__ P, const float4* __restrict__ bias,
    float4* __restrict__ C, int N4, int total4)
{
    int i = blockIdx.x * blockDim.x + threadIdx.x;
    if (i < total4) {
        float4 v = bias[i & (N4 - 1)];
        float4 t[KSPLIT];
#pragma unroll
        for (int p = 0; p < KSPLIT; p++) t[p] = P[(size_t)p * total4 + i];
#pragma unroll
        for (int p = 0; p < KSPLIT; p++) {
            v.x += t[p].x; v.y += t[p].y; v.z += t[p].z; v.w += t[p].w;
        }
        C[i] = v;
    }
}

// ---------------------------------------------------------------------------
// Page-streaming attention: block = (seq, page). All 16 heads per block.
// A token's KV row ([16 heads][128 dims] = 8KB) is read contiguously.
// ---------------------------------------------------------------------------
__global__ __launch_bounds__(256) void attn_part_kernel(
    const float* __restrict__ kv_cache,      // [2, NB, bs, h, d]
    const int* __restrict__ block_tables,    // [S, MAX_BLOCKS]
    const int* __restrict__ seq_lens,        // [S]
    const float* __restrict__ qbuf)          // [S, HIDDEN]
{
    const int s = blockIdx.x;
    const int p = blockIdx.y;
    const int tid = threadIdx.x;
    const int warp = tid >> 5;
    const int lane = tid & 31;

    const int L  = seq_lens[s];
    const int Lp = min(L - p * BLOCK_SIZE, BLOCK_SIZE);
    if (Lp <= 0) return;                     // combine never reads empty pages

    const int blk = __ldg(&block_tables[s * MAX_BLOCKS + p]);

    __shared__ float q[NUM_HEADS * HEAD_DIM];        // 8KB
    __shared__ float scores[NUM_HEADS * BLOCK_SIZE]; // 4KB  [h][t]
    __shared__ float red[8][NUM_HEADS];
    __shared__ float gmaxs[NUM_HEADS];
    __shared__ float lsums[NUM_HEADS];
    __shared__ float accbuf[8][8 * HEAD_DIM];        // 32KB

    // load q for all heads (2048 floats = 512 float4)
    ((float4*)q)[tid]       = ((const float4*)(qbuf + s * HIDDEN))[tid];
    ((float4*)q)[tid + 256] = ((const float4*)(qbuf + s * HIDDEN))[tid + 256];
    __syncthreads();

    const float* kpage = kv_cache + (size_t)blk * BLOCK_SIZE * HIDDEN;
    const float* vpage = kpage + (size_t)NUM_BLOCKS_KV * BLOCK_SIZE * HIDDEN;

    // ---- Pass 1: scores for all heads; warp = token (stride 8) ----
    float mymax = -INFINITY;      // lane h holds running max for head h (lane<16)
    for (int t = warp; t < Lp; t += 8) {
        const float* row = kpage + (size_t)t * HIDDEN + lane * 4;
        float sc_mine = 0.f;
#pragma unroll 4
        for (int h = 0; h < NUM_HEADS; h++) {
            float4 k4 = ldcs4(row + h * HEAD_DIM);
            float4 qh = *(const float4*)&q[h * HEAD_DIM + lane * 4];
            float d = qh.x * k4.x + qh.y * k4.y + qh.z * k4.z + qh.w * k4.w;
#pragma unroll
            for (int o = 16; o; o >>= 1) d += __shfl_xor_sync(0xffffffffu, d, o);
            d *= SCALE;
            if (lane == h) { mymax = fmaxf(mymax, d); sc_mine = d; }
        }
        if (lane < NUM_HEADS) scores[lane * BLOCK_SIZE + t] = sc_mine;
    }
    if (lane < NUM_HEADS) red[warp][lane] = mymax;
    __syncthreads();

    if (tid < NUM_HEADS) {
        float m = red[0][tid];
#pragma unroll
        for (int w = 1; w < 8; w++) m = fmaxf(m, red[w][tid]);
        gmaxs[tid] = m;
    }
    __syncthreads();

    // ---- exp + per-head sums: thread tid -> head tid>>4, 4 tokens ----
    {
        int h = tid >> 4, ii = tid & 15;
        float gm = gmaxs[h];
        float part = 0.f;
#pragma unroll
        for (int j = 0; j < 4; j++) {
            int t = ii * 4 + j;
            if (t < Lp) {
                float e = __expf(scores[h * BLOCK_SIZE + t] - gm);
                scores[h * BLOCK_SIZE + t] = e;
                part += e;
            }
        }
#pragma unroll
        for (int o = 8; o; o >>= 1) part += __shfl_xor_sync(0xffffffffu, part, o);
        if (ii == 0) lsums[h] = part;
    }
    __syncthreads();

    // ---- Pass 2: V accumulate; warp-pair = token, 8 heads per warp ----
    {
        const int g = warp & 1;          // head group (0: h0-7, 1: h8-15)
        float4 acc[8];
#pragma unroll
        for (int i = 0; i < 8; i++) acc[i] = make_float4(0.f, 0.f, 0.f, 0.f);

        for (int t = (warp >> 1); t < Lp; t += 4) {
            const float* row = vpage + (size_t)t * HIDDEN + g * (8 * HEAD_DIM) + lane * 4;
#pragma unroll
            for (int i = 0; i < 8; i++) {
                float w = scores[(g * 8 + i) * BLOCK_SIZE + t];
                float4 v4 = ldcs4(row + i * HEAD_DIM);
                acc[i].x += w * v4.x;
                acc[i].y += w * v4.y;
                acc[i].z += w * v4.z;
                acc[i].w += w * v4.w;
            }
        }
#pragma unroll
        for (int i = 0; i < 8; i++)
            *(float4*)&accbuf[warp][i * HEAD_DIM + lane * 4] = acc[i];
    }
    __syncthreads();

    // ---- final reduce (4 warp-partials per head) + write partials ----
#pragma unroll
    for (int e = 0; e < 8; e++) {
        int idx = tid + e * 256;          // 0..2047 = head*128 + dim
        int h = idx >> 7, d = idx & 127;
        int gg = h >> 3, i = h & 7;
        float sum = accbuf[gg][i * HEAD_DIM + d] + accbuf[gg + 2][i * HEAD_DIM + d]
                  + accbuf[gg + 4][i * HEAD_DIM + d] + accbuf[gg + 6][i * HEAD_DIM + d];
        g_pacc[((size_t)(s * NUM_HEADS + h) * PART + p) * HEAD_DIM + d] = sum;
    }
    if (tid < NUM_HEADS)
        g_pml[(s * NUM_HEADS + tid) * PART + p] = make_float2(gmaxs[tid], lsums[tid]);
}

// ---------------------------------------------------------------------------
// Combine: block = (seq, head), 256 threads. 8 warps each online-merge pages
// p = warp, warp+8, ... (<=4 serial steps), then 128-thread smem merge of 8.
// ---------------------------------------------------------------------------
__global__ __launch_bounds__(256) void attn_combine_kernel(
    const int* __restrict__ seq_lens, float* __restrict__ out)
{
    const int s = blockIdx.x;
    const int h = blockIdx.y;
    const int warp = threadIdx.x >> 5;
    const int lane = threadIdx.x & 31;
    const int base = (s * NUM_HEADS + h) * PART;
    const int nv = min((__ldg(&seq_lens[s]) + BLOCK_SIZE - 1) >> 6, PART);

    __shared__ float m8[8], l8[8];
    __shared__ float obuf[8][HEAD_DIM];

    float m = -INFINITY, l = 0.f;
    float4 o = make_float4(0.f, 0.f, 0.f, 0.f);
    for (int p = warp; p < nv; p += 8) {
        float2 ml = g_pml[base + p];
        float4 pa = *(const float4*)&g_pacc[(size_t)(base + p) * HEAD_DIM + lane * 4];
        if (ml.x > m) {
            float r = __expf(m - ml.x);
            l *= r; o.x *= r; o.y *= r; o.z *= r; o.w *= r;
            m = ml.x;
        }
        float sc = __expf(ml.x - m);
        l += ml.y * sc;
        o.x += pa.x * sc; o.y += pa.y * sc; o.z += pa.z * sc; o.w += pa.w * sc;
    }
    *(float4*)&obuf[warp][lane * 4] = o;
    if (lane == 0) { m8[warp] = m; l8[warp] = l; }
    __syncthreads();

    if (threadIdx.x < HEAD_DIM) {
        int d = threadIdx.x;
        float M = m8[0];
#pragma unroll
        for (int w = 1; w < 8; w++) M = fmaxf(M, m8[w]);
        float L = 0.f, O = 0.f;
#pragma unroll
        for (int w = 0; w < 8; w++) {
            float sc = (m8[w] == -INFINITY) ? 0.f : __expf(m8[w] - M);
            L += l8[w] * sc;
            O += obuf[w][d] * sc;
        }
        out[s * HIDDEN + h * HEAD_DIM + d] = O / L;
    }
}

// ---------------------------------------------------------------------------
extern "C" void kernel_launch(void* const* d_in, const int* in_sizes, int n_in,
                              void* d_out, int out_size)
{
    const float* hidden  = (const float*)d_in[0];
    const float* kvcache = (const float*)d_in[1];
    const float* W_attn  = (const float*)d_in[2];
    const float* b_attn  = (const float*)d_in[3];
    const float* W_proj  = (const float*)d_in[4];
    const float* b_proj  = (const float*)d_in[5];
    const int*   btab    = (const int*)d_in[6];
    const int*   slens   = (const int*)d_in[7];
    float* out = (float*)d_out;

    float *gq, *gattn, *gpart;
    cudaGetSymbolAddress((void**)&gq, g_q);
    cudaGetSymbolAddress((void**)&gattn, g_attn);
    cudaGetSymbolAddress((void**)&gpart, g_part);

    const int total4 = NUM_SEQS * HIDDEN / 4;  // 32768
    const int N4 = HIDDEN / 4;                 // 512

    // 1) Q projection only (first HIDDEN columns of W_attn), split-K=8
    gemm_splitk<<<dim3(HIDDEN / 64, KSPLIT), 256>>>(hidden, W_attn, gpart, HIDDEN, 3 * HIDDEN, HIDDEN);
    reduceK<<<(total4 + 255) / 256, 256>>>((const float4*)gpart, (const float4*)b_attn,
                                           (float4*)gq, N4, total4);

    // 2) paged attention: page-streaming split + combine
    attn_part_kernel<<<dim3(NUM_SEQS, PART), 256>>>(kvcache, btab, slens, gq);
    attn_combine_kernel<<<dim3(NUM_SEQS, NUM_HEADS), 256>>>(slens, gattn);

    // 3) output projection, split-K=8
    gemm_splitk<<<dim3(HIDDEN / 64, KSPLIT), 256>>>(gattn, W_proj, gpart, HIDDEN, HIDDEN, HIDDEN);
    reduceK<<<(total4 + 255) / 256, 256>>>((const float4*)gpart, (const float4*)b_proj,
                                           (float4*)out, N4, total4);
}

// round 9
// speedup vs baseline: 1.1932x; 1.0270x over previous
#include <cuda_runtime.h>
#include <math.h>
#include <stdint.h>

#define HIDDEN 2048
#define NUM_HEADS 16
#define HEAD_DIM 128
#define BLOCK_SIZE 64
#define NUM_SEQS 64
#define MAX_SEQ_LEN 2048
#define MAX_BLOCKS 32
#define NUM_BLOCKS_KV 2048
#define SCALE 0.08838834764831843f   // 1/sqrt(128)

#define KSPLIT 8
#define PART 32            // one KV page (64 tokens) per partition

// Scratch (device globals; no allocation allowed)
__device__ float g_q[NUM_SEQS * HIDDEN];                   // Q projection result
__device__ float g_attn[NUM_SEQS * HIDDEN];                // attention output
__device__ float g_part[KSPLIT * NUM_SEQS * HIDDEN];       // split-K partials
__device__ float g_pacc[NUM_SEQS * NUM_HEADS * PART * HEAD_DIM]; // attn partial accum
__device__ float2 g_pml[NUM_SEQS * NUM_HEADS * PART];      // attn partial (m, l)

__device__ __forceinline__ float4 ldcs4(const float* p) {
    return __ldcs((const float4*)p);
}

__device__ __forceinline__ uint32_t f2tf32(float f) {
    uint32_t r;
    asm("cvt.rna.tf32.f32 %0, %1;" : "=r"(r) : "f"(f));
    return r;
}

__device__ __forceinline__ void mma_tf32(float c[4],
    uint32_t a0, uint32_t a1, uint32_t a2, uint32_t a3,
    uint32_t b0, uint32_t b1)
{
    asm("mma.sync.aligned.m16n8k8.row.col.f32.tf32.tf32.f32 "
        "{%0,%1,%2,%3}, {%4,%5,%6,%7}, {%8,%9}, {%0,%1,%2,%3};"
        : "+f"(c[0]), "+f"(c[1]), "+f"(c[2]), "+f"(c[3])
        : "r"(a0), "r"(a1), "r"(a2), "r"(a3), "r"(b0), "r"(b1));
}

// ---------------------------------------------------------------------------
// Split-K tf32 tensor-core GEMM: P[ks] = A[64 x Kslice] @ B[K x N (ldb)]
// block = 128 threads (4 warps); tile 64M x 64N; warp = 16M x 64N.
// A/B staged in smem as tf32 (cvt.rna applied once at load).
// ---------------------------------------------------------------------------
__global__ __launch_bounds__(128) void gemm_splitk(
    const float* __restrict__ A, const float* __restrict__ B,
    float* __restrict__ P, int K, int ldb, int N)
{
    const int KS = K / KSPLIT;              // 256
    const int k_base = blockIdx.y * KS;
    const int n0 = blockIdx.x * 64;

    __shared__ uint32_t As[64][33];         // 64 rows x 32 k (padded)
    __shared__ uint32_t Bs[32][65];         // 32 k x 64 n (padded)

    const int tid  = threadIdx.x;
    const int warp = tid >> 5;
    const int lane = tid & 31;
    const int gid  = lane >> 2;             // 0..7
    const int ctid = lane & 3;              // 0..3
    const int wm   = warp * 16;             // warp's M offset

    float acc[8][4];
#pragma unroll
    for (int nt = 0; nt < 8; nt++)
#pragma unroll
        for (int j = 0; j < 4; j++) acc[nt][j] = 0.f;

    // gmem prefetch registers: A tile 64x32 = 512 f4, B tile 32x64 = 512 f4
    float4 ra[4], rb[4];
#pragma unroll
    for (int i = 0; i < 4; i++) {
        int f = i * 128 + tid;
        ra[i] = *(const float4*)&A[(f >> 3) * K + k_base + (f & 7) * 4];
        rb[i] = *(const float4*)&B[(size_t)(k_base + (f >> 4)) * ldb + n0 + (f & 15) * 4];
    }

    for (int k0 = k_base; k0 < k_base + KS; k0 += 32) {
        // stage tiles (convert to tf32 once)
#pragma unroll
        for (int i = 0; i < 4; i++) {
            int f = i * 128 + tid;
            int arow = f >> 3, ac = (f & 7) * 4;
            As[arow][ac + 0] = f2tf32(ra[i].x);
            As[arow][ac + 1] = f2tf32(ra[i].y);
            As[arow][ac + 2] = f2tf32(ra[i].z);
            As[arow][ac + 3] = f2tf32(ra[i].w);
            int brow = f >> 4, bc = (f & 15) * 4;
            Bs[brow][bc + 0] = f2tf32(rb[i].x);
            Bs[brow][bc + 1] = f2tf32(rb[i].y);
            Bs[brow][bc + 2] = f2tf32(rb[i].z);
            Bs[brow][bc + 3] = f2tf32(rb[i].w);
        }
        __syncthreads();

        if (k0 + 32 < k_base + KS) {
            int kn = k0 + 32;
#pragma unroll
            for (int i = 0; i < 4; i++) {
                int f = i * 128 + tid;
                ra[i] = *(const float4*)&A[(f >> 3) * K + kn + (f & 7) * 4];
                rb[i] = *(const float4*)&B[(size_t)(kn + (f >> 4)) * ldb + n0 + (f & 15) * 4];
            }
        }

#pragma unroll
        for (int kk = 0; kk < 32; kk += 8) {
            uint32_t a0 = As[wm + gid][kk + ctid];
            uint32_t a1 = As[wm + gid + 8][kk + ctid];
            uint32_t a2 = As[wm + gid][kk + ctid + 4];
            uint32_t a3 = As[wm + gid + 8][kk + ctid + 4];
#pragma unroll
            for (int nt = 0; nt < 8; nt++) {
                uint32_t b0 = Bs[kk + ctid][nt * 8 + gid];
                uint32_t b1 = Bs[kk + ctid + 4][nt * 8 + gid];
                mma_tf32(acc[nt], a0, a1, a2, a3, b0, b1);
            }
        }
        __syncthreads();
    }

    // epilogue: c0,c1 = (wm+gid, n0+nt*8+ctid*2 .. +1); c2,c3 = row+8
    float* Pp = P + (size_t)blockIdx.y * 64 * N;
#pragma unroll
    for (int nt = 0; nt < 8; nt++) {
        int col = n0 + nt * 8 + ctid * 2;
        *(float2*)&Pp[(wm + gid) * N + col]     = make_float2(acc[nt][0], acc[nt][1]);
        *(float2*)&Pp[(wm + gid + 8) * N + col] = make_float2(acc[nt][2], acc[nt][3]);
    }
}

// reduce KSPLIT partials + bias (float4 vectorized; MLP=8)
__global__ __launch_bounds__(256) void reduceK(
    const float4* __restrict__ P, const float4* __restrict__ bias,
    float4* __restrict__ C, int N4, int total4)
{
    int i = blockIdx.x * blockDim.x + threadIdx.x;
    if (i < total4) {
        float4 v = bias[i & (N4 - 1)];
        float4 t[KSPLIT];
#pragma unroll
        for (int p = 0; p < KSPLIT; p++) t[p] = P[(size_t)p * total4 + i];
#pragma unroll
        for (int p = 0; p < KSPLIT; p++) {
            v.x += t[p].x; v.y += t[p].y; v.z += t[p].z; v.w += t[p].w;
        }
        C[i] = v;
    }
}

// ---------------------------------------------------------------------------
// Page-streaming attention: block = (seq, page). All 16 heads per block.
// ---------------------------------------------------------------------------
__global__ __launch_bounds__(256) void attn_part_kernel(
    const float* __restrict__ kv_cache,      // [2, NB, bs, h, d]
    const int* __restrict__ block_tables,    // [S, MAX_BLOCKS]
    const int* __restrict__ seq_lens,        // [S]
    const float* __restrict__ qbuf)          // [S, HIDDEN]
{
    const int s = blockIdx.x;
    const int p = blockIdx.y;
    const int tid = threadIdx.x;
    const int warp = tid >> 5;
    const int lane = tid & 31;

    const int L  = seq_lens[s];
    const int Lp = min(L - p * BLOCK_SIZE, BLOCK_SIZE);
    if (Lp <= 0) return;

    const int blk = __ldg(&block_tables[s * MAX_BLOCKS + p]);

    __shared__ float q[NUM_HEADS * HEAD_DIM];        // 8KB
    __shared__ float scores[NUM_HEADS * BLOCK_SIZE]; // 4KB  [h][t]
    __shared__ float red[8][NUM_HEADS];
    __shared__ float gmaxs[NUM_HEADS];
    __shared__ float lsums[NUM_HEADS];
    __shared__ float accbuf[8][8 * HEAD_DIM];        // 32KB

    ((float4*)q)[tid]       = ((const float4*)(qbuf + s * HIDDEN))[tid];
    ((float4*)q)[tid + 256] = ((const float4*)(qbuf + s * HIDDEN))[tid + 256];
    __syncthreads();

    const float* kpage = kv_cache + (size_t)blk * BLOCK_SIZE * HIDDEN;
    const float* vpage = kpage + (size_t)NUM_BLOCKS_KV * BLOCK_SIZE * HIDDEN;

    // ---- Pass 1: scores for all heads; warp = token (stride 8) ----
    float mymax = -INFINITY;
    for (int t = warp; t < Lp; t += 8) {
        const float* row = kpage + (size_t)t * HIDDEN + lane * 4;
        float sc_mine = 0.f;
#pragma unroll 4
        for (int h = 0; h < NUM_HEADS; h++) {
            float4 k4 = ldcs4(row + h * HEAD_DIM);
            float4 qh = *(const float4*)&q[h * HEAD_DIM + lane * 4];
            float d = qh.x * k4.x + qh.y * k4.y + qh.z * k4.z + qh.w * k4.w;
#pragma unroll
            for (int o = 16; o; o >>= 1) d += __shfl_xor_sync(0xffffffffu, d, o);
            d *= SCALE;
            if (lane == h) { mymax = fmaxf(mymax, d); sc_mine = d; }
        }
        if (lane < NUM_HEADS) scores[lane * BLOCK_SIZE + t] = sc_mine;
    }
    if (lane < NUM_HEADS) red[warp][lane] = mymax;
    __syncthreads();

    if (tid < NUM_HEADS) {
        float m = red[0][tid];
#pragma unroll
        for (int w = 1; w < 8; w++) m = fmaxf(m, red[w][tid]);
        gmaxs[tid] = m;
    }
    __syncthreads();

    // ---- exp + per-head sums ----
    {
        int h = tid >> 4, ii = tid & 15;
        float gm = gmaxs[h];
        float part = 0.f;
#pragma unroll
        for (int j = 0; j < 4; j++) {
            int t = ii * 4 + j;
            if (t < Lp) {
                float e = __expf(scores[h * BLOCK_SIZE + t] - gm);
                scores[h * BLOCK_SIZE + t] = e;
                part += e;
            }
        }
#pragma unroll
        for (int o = 8; o; o >>= 1) part += __shfl_xor_sync(0xffffffffu, part, o);
        if (ii == 0) lsums[h] = part;
    }
    __syncthreads();

    // ---- Pass 2: V accumulate; warp-pair = token, 8 heads per warp ----
    {
        const int g = warp & 1;
        float4 acc[8];
#pragma unroll
        for (int i = 0; i < 8; i++) acc[i] = make_float4(0.f, 0.f, 0.f, 0.f);

        for (int t = (warp >> 1); t < Lp; t += 4) {
            const float* row = vpage + (size_t)t * HIDDEN + g * (8 * HEAD_DIM) + lane * 4;
#pragma unroll
            for (int i = 0; i < 8; i++) {
                float w = scores[(g * 8 + i) * BLOCK_SIZE + t];
                float4 v4 = ldcs4(row + i * HEAD_DIM);
                acc[i].x += w * v4.x;
                acc[i].y += w * v4.y;
                acc[i].z += w * v4.z;
                acc[i].w += w * v4.w;
            }
        }
#pragma unroll
        for (int i = 0; i < 8; i++)
            *(float4*)&accbuf[warp][i * HEAD_DIM + lane * 4] = acc[i];
    }
    __syncthreads();

    // ---- final reduce + write partials ----
#pragma unroll
    for (int e = 0; e < 8; e++) {
        int idx = tid + e * 256;
        int h = idx >> 7, d = idx & 127;
        int gg = h >> 3, i = h & 7;
        float sum = accbuf[gg][i * HEAD_DIM + d] + accbuf[gg + 2][i * HEAD_DIM + d]
                  + accbuf[gg + 4][i * HEAD_DIM + d] + accbuf[gg + 6][i * HEAD_DIM + d];
        g_pacc[((size_t)(s * NUM_HEADS + h) * PART + p) * HEAD_DIM + d] = sum;
    }
    if (tid < NUM_HEADS)
        g_pml[(s * NUM_HEADS + tid) * PART + p] = make_float2(gmaxs[tid], lsums[tid]);
}

// ---------------------------------------------------------------------------
// Combine: block = (seq, head), 256 threads. Each warp batch-loads its <=4
// pages with independent predicated LDGs (no load->exp->load chain), merges
// in registers, then a 128-thread smem merge of the 8 warp partials.
// ---------------------------------------------------------------------------
__global__ __launch_bounds__(256) void attn_combine_kernel(
    const int* __restrict__ seq_lens, float* __restrict__ out)
{
    const int s = blockIdx.x;
    const int h = blockIdx.y;
    const int warp = threadIdx.x >> 5;
    const int lane = threadIdx.x & 31;
    const int base = (s * NUM_HEADS + h) * PART;
    const int nv = min((__ldg(&seq_lens[s]) + BLOCK_SIZE - 1) >> 6, PART);

    __shared__ float m8[8], l8[8];
    __shared__ float obuf[8][HEAD_DIM];

    // batch-load up to 4 pages (independent loads)
    float2 mlv[4];
    float4 pav[4];
#pragma unroll
    for (int j = 0; j < 4; j++) {
        int p = warp + j * 8;
        bool v = p < nv;
        mlv[j] = v ? g_pml[base + p] : make_float2(-INFINITY, 0.f);
        pav[j] = v ? *(const float4*)&g_pacc[(size_t)(base + p) * HEAD_DIM + lane * 4]
                   : make_float4(0.f, 0.f, 0.f, 0.f);
    }

    // register merge
    float m = -INFINITY, l = 0.f;
    float4 o = make_float4(0.f, 0.f, 0.f, 0.f);
#pragma unroll
    for (int j = 0; j < 4; j++) {
        if (mlv[j].x > m) {
            float r = __expf(m - mlv[j].x);
            l *= r; o.x *= r; o.y *= r; o.z *= r; o.w *= r;
            m = mlv[j].x;
        }
        float sc = (mlv[j].x == -INFINITY) ? 0.f : __expf(mlv[j].x - m);
        l += mlv[j].y * sc;
        o.x += pav[j].x * sc; o.y += pav[j].y * sc;
        o.z += pav[j].z * sc; o.w += pav[j].w * sc;
    }

    *(float4*)&obuf[warp][lane * 4] = o;
    if (lane == 0) { m8[warp] = m; l8[warp] = l; }
    __syncthreads();

    if (threadIdx.x < HEAD_DIM) {
        int d = threadIdx.x;
        float M = m8[0];
#pragma unroll
        for (int w = 1; w < 8; w++) M = fmaxf(M, m8[w]);
        float L = 0.f, O = 0.f;
#pragma unroll
        for (int w = 0; w < 8; w++) {
            float sc = (m8[w] == -INFINITY) ? 0.f : __expf(m8[w] - M);
            L += l8[w] * sc;
            O += obuf[w][d] * sc;
        }
        out[s * HIDDEN + h * HEAD_DIM + d] = O / L;
    }
}

// ---------------------------------------------------------------------------
extern "C" void kernel_launch(void* const* d_in, const int* in_sizes, int n_in,
                              void* d_out, int out_size)
{
    const float* hidden  = (const float*)d_in[0];
    const float* kvcache = (const float*)d_in[1];
    const float* W_attn  = (const float*)d_in[2];
    const float* b_attn  = (const float*)d_in[3];
    const float* W_proj  = (const float*)d_in[4];
    const float* b_proj  = (const float*)d_in[5];
    const int*   btab    = (const int*)d_in[6];
    const int*   slens   = (const int*)d_in[7];
    float* out = (float*)d_out;

    float *gq, *gattn, *gpart;
    cudaGetSymbolAddress((void**)&gq, g_q);
    cudaGetSymbolAddress((void**)&gattn, g_attn);
    cudaGetSymbolAddress((void**)&gpart, g_part);

    const int total4 = NUM_SEQS * HIDDEN / 4;  // 32768
    const int N4 = HIDDEN / 4;                 // 512

    // 1) Q projection only (first HIDDEN columns of W_attn), tf32 tensor cores
    gemm_splitk<<<dim3(HIDDEN / 64, KSPLIT), 128>>>(hidden, W_attn, gpart, HIDDEN, 3 * HIDDEN, HIDDEN);
    reduceK<<<(total4 + 255) / 256, 256>>>((const float4*)gpart, (const float4*)b_attn,
                                           (float4*)gq, N4, total4);

    // 2) paged attention: page-streaming split + combine
    attn_part_kernel<<<dim3(NUM_SEQS, PART), 256>>>(kvcache, btab, slens, gq);
    attn_combine_kernel<<<dim3(NUM_SEQS, NUM_HEADS), 256>>>(slens, gattn);

    // 3) output projection, tf32 tensor cores
    gemm_splitk<<<dim3(HIDDEN / 64, KSPLIT), 128>>>(gattn, W_proj, gpart, HIDDEN, HIDDEN, HIDDEN);
    reduceK<<<(total4 + 255) / 256, 256>>>((const float4*)gpart, (const float4*)b_proj,
                                           (float4*)out, N4, total4);
}